// round 13
// baseline (speedup 1.0000x reference)
#include <cuda_runtime.h>
#include <cstdint>
#include <cstddef>

#define NB 8
#define NN 2048
#define MM 256
#define GG 1024  // 4*MM

// ---------------- device-global scratch (no allocations allowed) -----------
__device__ float g_H[NB * NN * MM];   // h_t per (batch, step)   16 MB
__device__ float g_Q[NB * NN * MM];   // q_t per (batch, step)   16 MB
__device__ float g_K[NB * NN * MM];   // keys                    16 MB
__device__ float g_xb[GG];            // x_proj + b_ih + b_hh
__device__ int   g_rank[NB * NN];     // step at which index was selected

// ---------------- helpers --------------------------------------------------
__device__ __forceinline__ uint32_t smem_u32(const void* p) {
    return (uint32_t)__cvta_generic_to_shared(p);
}
__device__ __forceinline__ uint32_t mapa_rank(uint32_t laddr, uint32_t rank) {
    uint32_t r;
    asm("mapa.shared::cluster.u32 %0, %1, %2;" : "=r"(r) : "r"(laddr), "r"(rank));
    return r;
}
__device__ __forceinline__ void st_cluster_f32(uint32_t addr, float v) {
    asm volatile("st.shared::cluster.f32 [%0], %1;" :: "r"(addr), "f"(v) : "memory");
}
__device__ __forceinline__ void cluster_sync_() {
    asm volatile("barrier.cluster.arrive.aligned;" ::: "memory");
    asm volatile("barrier.cluster.wait.aligned;" ::: "memory");
}
__device__ __forceinline__ void mbar_init(uint32_t addr, uint32_t cnt) {
    asm volatile("mbarrier.init.shared.b64 [%0], %1;" :: "r"(addr), "r"(cnt) : "memory");
}
__device__ __forceinline__ void fence_cluster_() {
    asm volatile("fence.acq_rel.cluster;" ::: "memory");
}
__device__ __forceinline__ void mbar_arrive_remote(uint32_t addr) {
    asm volatile("mbarrier.arrive.release.cluster.shared::cluster.b64 _, [%0];"
                 :: "r"(addr) : "memory");
}
__device__ __forceinline__ void mbar_wait(uint32_t addr, uint32_t parity) {
    uint32_t done;
    asm volatile(
        "{\n\t.reg .pred p;\n\t"
        "mbarrier.try_wait.parity.acquire.cluster.shared::cta.b64 p, [%1], %2;\n\t"
        "selp.b32 %0, 1, 0, p;\n\t}"
        : "=r"(done) : "r"(addr), "r"(parity) : "memory");
    while (!done) {
        asm volatile(
            "{\n\t.reg .pred p;\n\t"
            "mbarrier.try_wait.parity.acquire.cluster.shared::cta.b64 p, [%1], %2, 0x989680;\n\t"
            "selp.b32 %0, 1, 0, p;\n\t}"
            : "=r"(done) : "r"(addr), "r"(parity) : "memory");
    }
}
__device__ __forceinline__ uint32_t fkey(float f) {
    uint32_t u = __float_as_uint(f);
    return (u & 0x80000000u) ? ~u : (u | 0x80000000u);  // monotonic float->uint
}
__device__ __forceinline__ float sigm(float x) { return 1.0f / (1.0f + expf(-x)); }

// packed f32x2 ops (sm_103a; ptxas never auto-fuses these)
__device__ __forceinline__ uint64_t fma2(uint64_t a, uint64_t b, uint64_t c) {
    uint64_t d;
    asm("fma.rn.f32x2 %0, %1, %2, %3;" : "=l"(d) : "l"(a), "l"(b), "l"(c));
    return d;
}
__device__ __forceinline__ uint64_t add2(uint64_t a, uint64_t b) {
    uint64_t d;
    asm("add.rn.f32x2 %0, %1, %2;" : "=l"(d) : "l"(a), "l"(b));
    return d;
}
__device__ __forceinline__ uint64_t pack2(float lo, float hi) {
    uint64_t d;
    asm("mov.b64 %0, {%1, %2};" : "=l"(d) : "r"(__float_as_uint(lo)), "r"(__float_as_uint(hi)));
    return d;
}
__device__ __forceinline__ float unpack_sum(uint64_t a) {
    uint32_t lo, hi;
    asm("mov.b64 {%0, %1}, %2;" : "=r"(lo), "=r"(hi) : "l"(a));
    return __uint_as_float(lo) + __uint_as_float(hi);
}
__device__ __forceinline__ void unpack2(uint64_t a, float& lo, float& hi) {
    uint32_t l, h;
    asm("mov.b64 {%0, %1}, %2;" : "=r"(l), "=r"(h) : "l"(a));
    lo = __uint_as_float(l); hi = __uint_as_float(h);
}

// ---------------- dummy (slot #3 so k_lstm is launch #4 for ncu) -----------
__global__ void k_dummy() { if (threadIdx.x == 0) g_Q[0] = 0.0f; }

// ---------------- setup: g_xb = w_ih @ dec + b_ih + b_hh -------------------
__global__ void __launch_bounds__(1024) k_setup(
    const float* __restrict__ w_ih, const float* __restrict__ b_ih,
    const float* __restrict__ b_hh, const float* __restrict__ dec) {
    __shared__ __align__(16) float ds[MM];
    int g = threadIdx.x;
    if (g < MM) ds[g] = dec[g];
    __syncthreads();
    const float4* w4 = (const float4*)(w_ih + (size_t)g * MM);
    const float4* d4 = (const float4*)ds;
    float acc = 0.f;
#pragma unroll 16
    for (int i = 0; i < MM / 4; i++) {
        float4 w = w4[i], d = d4[i];
        acc += w.x * d.x + w.y * d.y + w.z * d.z + w.w * d.w;
    }
    g_xb[g] = acc + b_ih[g] + b_hh[g];
}

// ---------------- phase 1: LSTM scan, 8-CTA cluster per batch --------------
// CTA rank r owns h elements [r*32, r*32+32). Per step:
//   wait(mbar, fast-path ~90cyc) -> gate GEMV (reg weights, packed f32x2)
//   -> syncthreads -> PARALLEL activations (128 threads, 1 transcendental ea.)
//   -> syncthreads -> owner c/h update -> 8 remote h stores
//   -> syncwarp -> fence.acq_rel.cluster -> tid0: 8 remote mbar arrives.
// Barrier count = 8 (one elected arrive per producer CTA), double-buffered.
__global__ void __cluster_dims__(8, 1, 1) __launch_bounds__(256, 1)
k_lstm(const float* __restrict__ w_hh, const float* __restrict__ z_g,
       const float* __restrict__ h0) {
    int tid = threadIdx.x;
    uint32_t rk;
    asm("mov.u32 %0, %%cluster_ctarank;" : "=r"(rk));
    int b = blockIdx.x >> 3;

    __shared__ __align__(16) float h_sm[2][MM];          // cluster-written
    __shared__ __align__(16) float gloc[128];            // raw gates
    __shared__ __align__(16) float gact[128];            // activated gates
    __shared__ __align__(8) unsigned long long mbar_sm[2];

    // gate shard: row rloc = tid>>1, kh = K-half; math identical to R8/R11/R12
    int rloc = tid >> 1;
    int kh = tid & 1;
    int g4 = rloc >> 5, j = rloc & 31;
    int grow = g4 * 256 + (int)rk * 32 + j;
    uint64_t wg[64];
    {
        const uint64_t* wp = (const uint64_t*)(w_hh + (size_t)grow * MM + kh * 128);
#pragma unroll
        for (int i = 0; i < 64; i++) wg[i] = wp[i];
    }
    float xb = g_xb[grow];

    // remote addresses
    uint32_t ha[8], rm0[8], rm1[8];
    {
        uint32_t la = smem_u32(&h_sm[0][0]);
        uint32_t lb0 = smem_u32(&mbar_sm[0]);
#pragma unroll
        for (int r = 0; r < 8; r++) {
            ha[r] = mapa_rank(la, (uint32_t)r);
            rm0[r] = mapa_rank(lb0, (uint32_t)r);
            rm1[r] = rm0[r] + 8;
        }
    }

    if (tid == 0) { mbar_init(smem_u32(&mbar_sm[0]), 8); mbar_init(smem_u32(&mbar_sm[1]), 8); }
    h_sm[0][tid] = h0[tid];
    float c_reg = 0.f;
    if (tid < 32) c_reg = z_g[b * MM + (int)rk * 32 + tid];
    __syncthreads();
    cluster_sync_();   // mbarriers initialized everywhere before any remote arrive

    float* Hb = g_H + (size_t)b * NN * MM;
    uint32_t mb0 = smem_u32(&mbar_sm[0]);

    for (int t = 0; t < NN; t++) {
        if (t > 0) {
            // all 8 producer CTAs arrived for h of step t (buffer t&1)
            mbar_wait(mb0 + (uint32_t)((t & 1) * 8), (uint32_t)(((t - 1) >> 1) & 1));
        }

        // ---- gate GEMV (LDS.128 + packed FMAs) ----------------------------
        {
            const ulonglong2* h4 = (const ulonglong2*)(h_sm[t & 1] + kh * 128);
            uint64_t a0 = 0, a1 = 0, a2 = 0, a3 = 0;
#pragma unroll
            for (int i = 0; i < 32; i += 2) {
                ulonglong2 v0 = h4[i], v1 = h4[i + 1];
                a0 = fma2(wg[2 * i + 0], v0.x, a0);
                a1 = fma2(wg[2 * i + 1], v0.y, a1);
                a2 = fma2(wg[2 * i + 2], v1.x, a2);
                a3 = fma2(wg[2 * i + 3], v1.y, a3);
            }
            float s = unpack_sum(add2(add2(a0, a1), add2(a2, a3)));
            s += __shfl_xor_sync(0xffffffffu, s, 1);
            if (kh == 0) gloc[rloc] = s + xb;
        }
        __syncthreads();

        // ---- parallel activations: one transcendental per (kh==0) thread --
        // g4 is warp-uniform (warp w covers rloc [16w,16w+16), g4 = w>>1).
        if (kh == 0) {
            float v = gloc[rloc];
            gact[rloc] = (g4 == 2) ? tanhf(v) : sigm(v);
        }
        __syncthreads();

        // ---- owner c/h update + broadcast + g_H store ----------------------
        if (tid < 32) {
            float ai = gact[tid], af = gact[32 + tid];
            float ag = gact[64 + tid], ao = gact[96 + tid];
            float c = af * c_reg + ai * ag;
            c_reg = c;
            float hv = ao * tanhf(c);
            Hb[(size_t)t * MM + (int)rk * 32 + tid] = hv;
            if (t + 1 < NN) {
                uint32_t hoff = (uint32_t)(((((t + 1) & 1) * MM) + (int)rk * 32 + tid) * 4);
#pragma unroll
                for (int r = 0; r < 8; r++) st_cluster_f32(ha[r] + hoff, hv);
                __syncwarp();
                if (tid == 0) {
                    fence_cluster_();   // publish all 32 lanes' remote stores
                    if ((t + 1) & 1) {
#pragma unroll
                        for (int r = 0; r < 8; r++) mbar_arrive_remote(rm1[r]);
                    } else {
#pragma unroll
                        for (int r = 0; r < 8; r++) mbar_arrive_remote(rm0[r]);
                    }
                }
            }
        }
    }
}

// ---------------- phase 2: C = A @ B^T (+bias), K=256, packed f32x2 --------
__global__ void __launch_bounds__(256) k_gemm_nt(
    const float* __restrict__ A, const float* __restrict__ B,
    const float* __restrict__ bias, float* __restrict__ C,
    size_t sA, size_t sB, size_t sC, int ldc) {
    A += (size_t)blockIdx.z * sA;
    B += (size_t)blockIdx.z * sB;
    C += (size_t)blockIdx.z * sC;
    int row0 = blockIdx.y * 128, col0 = blockIdx.x * 128;

    __shared__ __align__(16) float As[16][132];
    __shared__ __align__(16) float Bs[16][132];

    int tid = threadIdx.x;
    int tx = tid & 15, ty = tid >> 4;
    uint64_t acc2[8][4] = {};

    for (int kt = 0; kt < 256; kt += 16) {
#pragma unroll
        for (int l = 0; l < 2; l++) {
            int f = tid + 256 * l;
            int i = f >> 2, c4 = (f & 3) * 4;
            float4 a = *(const float4*)(A + (size_t)(row0 + i) * 256 + kt + c4);
            As[c4 + 0][i] = a.x; As[c4 + 1][i] = a.y; As[c4 + 2][i] = a.z; As[c4 + 3][i] = a.w;
            float4 bv = *(const float4*)(B + (size_t)(col0 + i) * 256 + kt + c4);
            Bs[c4 + 0][i] = bv.x; Bs[c4 + 1][i] = bv.y; Bs[c4 + 2][i] = bv.z; Bs[c4 + 3][i] = bv.w;
        }
        __syncthreads();
#pragma unroll
        for (int kk = 0; kk < 16; kk++) {
            float4 t0 = *(const float4*)(&As[kk][ty * 8]);
            float4 t1 = *(const float4*)(&As[kk][ty * 8 + 4]);
            uint64_t ad[8];
            ad[0] = pack2(t0.x, t0.x); ad[1] = pack2(t0.y, t0.y);
            ad[2] = pack2(t0.z, t0.z); ad[3] = pack2(t0.w, t0.w);
            ad[4] = pack2(t1.x, t1.x); ad[5] = pack2(t1.y, t1.y);
            ad[6] = pack2(t1.z, t1.z); ad[7] = pack2(t1.w, t1.w);
            const uint64_t* bsp = (const uint64_t*)(&Bs[kk][tx * 8]);
            uint64_t bp0 = bsp[0], bp1 = bsp[1], bp2 = bsp[2], bp3 = bsp[3];
#pragma unroll
            for (int i = 0; i < 8; i++) {
                acc2[i][0] = fma2(ad[i], bp0, acc2[i][0]);
                acc2[i][1] = fma2(ad[i], bp1, acc2[i][1]);
                acc2[i][2] = fma2(ad[i], bp2, acc2[i][2]);
                acc2[i][3] = fma2(ad[i], bp3, acc2[i][3]);
            }
        }
        __syncthreads();
    }

    float bs[8];
#pragma unroll
    for (int jj = 0; jj < 8; jj++) bs[jj] = bias ? bias[col0 + tx * 8 + jj] : 0.f;

#pragma unroll
    for (int i = 0; i < 8; i++) {
        float v[8];
#pragma unroll
        for (int jp = 0; jp < 4; jp++) unpack2(acc2[i][jp], v[2 * jp], v[2 * jp + 1]);
        float* cp = C + (size_t)(row0 + ty * 8 + i) * ldc + col0 + tx * 8;
        float4 v0 = make_float4(v[0] + bs[0], v[1] + bs[1], v[2] + bs[2], v[3] + bs[3]);
        float4 v1 = make_float4(v[4] + bs[4], v[5] + bs[5], v[6] + bs[6], v[7] + bs[7]);
        *(float4*)cp = v0;
        *(float4*)(cp + 4) = v1;
    }
}

// ---------------- phase 3a: serial masked-argmax chain (selection only) ----
__global__ void __launch_bounds__(1024, 1) k_select(const float* __restrict__ S) {
    int b = blockIdx.x;
    int tid = threadIdx.x;
    int lane = tid & 31, warp = tid >> 5;
    const float* base = S + (size_t)b * NN * NN;
    int n0 = tid * 2;
    bool u0 = false, u1 = false;
    int* rkb = g_rank + b * NN;

    __shared__ uint32_t kmax_s[2][32];
    __shared__ uint32_t kidx_s[2][32];

    auto step = [&](int t, float2 cur) {
        uint32_t k0 = u0 ? 0u : fkey(cur.x);
        uint32_t k1 = u1 ? 0u : fkey(cur.y);
        uint32_t km = k0 > k1 ? k0 : k1;
        uint32_t wmax = __reduce_max_sync(0xffffffffu, km);
        uint32_t ci = 0xffffffffu;
        if (k0 == wmax) ci = (uint32_t)n0;
        else if (k1 == wmax) ci = (uint32_t)(n0 + 1);
        uint32_t widx = __reduce_min_sync(0xffffffffu, ci);
        if (lane == 0) { kmax_s[t & 1][warp] = wmax; kidx_s[t & 1][warp] = widx; }
        __syncthreads();
        uint32_t vm = kmax_s[t & 1][lane];
        uint32_t vi = kidx_s[t & 1][lane];
        uint32_t gmax = __reduce_max_sync(0xffffffffu, vm);
        uint32_t ci2 = (vm == gmax) ? vi : 0xffffffffu;
        uint32_t gidx = __reduce_min_sync(0xffffffffu, ci2);
        if (gidx == (uint32_t)n0)            { u0 = true; rkb[n0] = t; }
        else if (gidx == (uint32_t)(n0 + 1)) { u1 = true; rkb[n0 + 1] = t; }
    };

    float2 r0 = *(const float2*)(base + (size_t)0 * NN + n0);
    float2 r1 = *(const float2*)(base + (size_t)1 * NN + n0);
    float2 r2 = *(const float2*)(base + (size_t)2 * NN + n0);
    float2 r3 = *(const float2*)(base + (size_t)3 * NN + n0);

    for (int t = 0; t < NN; t += 4) {
        step(t + 0, r0);
        if (t + 4 < NN) r0 = *(const float2*)(base + (size_t)(t + 4) * NN + n0);
        step(t + 1, r1);
        if (t + 5 < NN) r1 = *(const float2*)(base + (size_t)(t + 5) * NN + n0);
        step(t + 2, r2);
        if (t + 6 < NN) r2 = *(const float2*)(base + (size_t)(t + 6) * NN + n0);
        step(t + 3, r3);
        if (t + 7 < NN) r3 = *(const float2*)(base + (size_t)(t + 7) * NN + n0);
    }
}

// ---------------- phase 3b: fully parallel masked softmax ------------------
__global__ void __launch_bounds__(256) k_probs(float* __restrict__ out) {
    int t = blockIdx.x, b = blockIdx.y;
    float* row = out + ((size_t)b * NN + t) * NN;
    const int* rkb = g_rank + b * NN;
    int tid = threadIdx.x;
    int lane = tid & 31, warp = tid >> 5;

    __shared__ float ps[8];
    float e[8];
    float s = 0.f;
#pragma unroll
    for (int jj = 0; jj < 2; jj++) {
        int i = tid * 4 + jj * 1024;
        float4 v = *(const float4*)(row + i);
        int4 r = *(const int4*)(rkb + i);
        float e0 = (r.x >= t) ? __expf(v.x) : 0.f;
        float e1 = (r.y >= t) ? __expf(v.y) : 0.f;
        float e2 = (r.z >= t) ? __expf(v.z) : 0.f;
        float e3 = (r.w >= t) ? __expf(v.w) : 0.f;
        e[jj * 4 + 0] = e0; e[jj * 4 + 1] = e1;
        e[jj * 4 + 2] = e2; e[jj * 4 + 3] = e3;
        s += (e0 + e1) + (e2 + e3);
    }
#pragma unroll
    for (int m = 16; m; m >>= 1) s += __shfl_xor_sync(0xffffffffu, s, m);
    if (lane == 0) ps[warp] = s;
    __syncthreads();
    float tot = ((ps[0] + ps[1]) + (ps[2] + ps[3]))
              + ((ps[4] + ps[5]) + (ps[6] + ps[7]));
    float inv = __fdividef(1.f, tot);
#pragma unroll
    for (int jj = 0; jj < 2; jj++) {
        int i = tid * 4 + jj * 1024;
        *(float4*)(row + i) = make_float4(e[jj * 4 + 0] * inv, e[jj * 4 + 1] * inv,
                                          e[jj * 4 + 2] * inv, e[jj * 4 + 3] * inv);
    }
}

// ---------------- launch ---------------------------------------------------
extern "C" void kernel_launch(void* const* d_in, const int* in_sizes, int n_in,
                              void* d_out, int out_size) {
    const float* node = (const float*)d_in[0];
    const float* z_g  = (const float*)d_in[1];
    const float* dec  = (const float*)d_in[2];
    const float* h0   = (const float*)d_in[3];
    const float* w_ih = (const float*)d_in[4];
    const float* w_hh = (const float*)d_in[5];
    const float* b_ih = (const float*)d_in[6];
    const float* b_hh = (const float*)d_in[7];
    const float* Wq   = (const float*)d_in[8];
    const float* bq   = (const float*)d_in[9];
    const float* Wk   = (const float*)d_in[10];
    const float* bk   = (const float*)d_in[11];
    float* out = (float*)d_out;

    float* dH = nullptr;
    float* dQ = nullptr;
    float* dK = nullptr;
    cudaGetSymbolAddress((void**)&dH, g_H);
    cudaGetSymbolAddress((void**)&dQ, g_Q);
    cudaGetSymbolAddress((void**)&dK, g_K);

    // #1 keys = node_emb @ Wk^T + bk
    k_gemm_nt<<<dim3(2, 128, 1), 256>>>(node, Wk, bk, dK, 0, 0, 0, 256);

    // #2 setup (x_proj + biases)
    k_setup<<<1, 1024>>>(w_ih, b_ih, b_hh, dec);

    // #3 dummy (positions k_lstm as launch #4 for the ncu capture window)
    k_dummy<<<1, 32>>>();

    // #4 LSTM scan -> g_H
    k_lstm<<<64, 256>>>(w_hh, z_g, h0);

    // #5 Q = H @ Wq^T + bq
    k_gemm_nt<<<dim3(2, 128, 1), 256>>>(dH, Wq, bq, dQ, 0, 0, 0, 256);

    // #6 S = Q @ K^T straight into d_out (per batch)
    k_gemm_nt<<<dim3(16, 16, 8), 256>>>(dQ, dK, nullptr, out,
                                        (size_t)NN * MM, (size_t)NN * MM,
                                        (size_t)NN * NN, NN);

    // #7 serial selection chain -> g_rank
    k_select<<<8, 1024>>>(out);

    // #8 fully parallel masked softmax, in place
    k_probs<<<dim3(NN, NB), 256>>>(out);
}

// round 14
// speedup vs baseline: 1.6278x; 1.6278x over previous
#include <cuda_runtime.h>
#include <cstdint>
#include <cstddef>

#define NB 8
#define NN 2048
#define MM 256
#define GG 1024  // 4*MM

// ---------------- device-global scratch (no allocations allowed) -----------
__device__ float g_H[NB * NN * MM];   // h_t per (batch, step)   16 MB
__device__ float g_Q[NB * NN * MM];   // q_t per (batch, step)   16 MB
__device__ float g_K[NB * NN * MM];   // keys                    16 MB
__device__ float g_xb[GG];            // x_proj + b_ih + b_hh
__device__ int   g_rank[NB * NN];     // step at which index was selected

// ---------------- helpers --------------------------------------------------
__device__ __forceinline__ uint32_t smem_u32(const void* p) {
    return (uint32_t)__cvta_generic_to_shared(p);
}
__device__ __forceinline__ uint32_t mapa_rank(uint32_t laddr, uint32_t rank) {
    uint32_t r;
    asm("mapa.shared::cluster.u32 %0, %1, %2;" : "=r"(r) : "r"(laddr), "r"(rank));
    return r;
}
__device__ __forceinline__ void st_cluster_f32(uint32_t addr, float v) {
    asm volatile("st.shared::cluster.f32 [%0], %1;" :: "r"(addr), "f"(v) : "memory");
}
__device__ __forceinline__ void st_release_u32(uint32_t addr, uint32_t v) {
    asm volatile("st.release.cluster.shared::cluster.u32 [%0], %1;"
                 :: "r"(addr), "r"(v) : "memory");
}
__device__ __forceinline__ uint32_t ld_acquire_u32(uint32_t addr) {
    uint32_t v;
    asm volatile("ld.acquire.cluster.shared::cta.u32 %0, [%1];"
                 : "=r"(v) : "r"(addr) : "memory");
    return v;
}
__device__ __forceinline__ void cluster_sync_() {
    asm volatile("barrier.cluster.arrive.aligned;" ::: "memory");
    asm volatile("barrier.cluster.wait.aligned;" ::: "memory");
}
__device__ __forceinline__ uint32_t fkey(float f) {
    uint32_t u = __float_as_uint(f);
    return (u & 0x80000000u) ? ~u : (u | 0x80000000u);  // monotonic float->uint
}
__device__ __forceinline__ float sigm(float x) { return 1.0f / (1.0f + expf(-x)); }

// packed f32x2 ops (sm_103a; ptxas never auto-fuses these)
__device__ __forceinline__ uint64_t fma2(uint64_t a, uint64_t b, uint64_t c) {
    uint64_t d;
    asm("fma.rn.f32x2 %0, %1, %2, %3;" : "=l"(d) : "l"(a), "l"(b), "l"(c));
    return d;
}
__device__ __forceinline__ uint64_t add2(uint64_t a, uint64_t b) {
    uint64_t d;
    asm("add.rn.f32x2 %0, %1, %2;" : "=l"(d) : "l"(a), "l"(b));
    return d;
}
__device__ __forceinline__ uint64_t pack2(float lo, float hi) {
    uint64_t d;
    asm("mov.b64 %0, {%1, %2};" : "=l"(d) : "r"(__float_as_uint(lo)), "r"(__float_as_uint(hi)));
    return d;
}
__device__ __forceinline__ float unpack_sum(uint64_t a) {
    uint32_t lo, hi;
    asm("mov.b64 {%0, %1}, %2;" : "=r"(lo), "=r"(hi) : "l"(a));
    return __uint_as_float(lo) + __uint_as_float(hi);
}
__device__ __forceinline__ void unpack2(uint64_t a, float& lo, float& hi) {
    uint32_t l, h;
    asm("mov.b64 {%0, %1}, %2;" : "=r"(l), "=r"(h) : "l"(a));
    lo = __uint_as_float(l); hi = __uint_as_float(h);
}

// ---------------- dummy (slot #3 so k_lstm is launch #4 for ncu) -----------
__global__ void k_dummy() { if (threadIdx.x == 0) g_Q[0] = 0.0f; }

// ---------------- setup: g_xb = w_ih @ dec + b_ih + b_hh -------------------
__global__ void __launch_bounds__(1024) k_setup(
    const float* __restrict__ w_ih, const float* __restrict__ b_ih,
    const float* __restrict__ b_hh, const float* __restrict__ dec) {
    __shared__ __align__(16) float ds[MM];
    int g = threadIdx.x;
    if (g < MM) ds[g] = dec[g];
    __syncthreads();
    const float4* w4 = (const float4*)(w_ih + (size_t)g * MM);
    const float4* d4 = (const float4*)ds;
    float acc = 0.f;
#pragma unroll 16
    for (int i = 0; i < MM / 4; i++) {
        float4 w = w4[i], d = d4[i];
        acc += w.x * d.x + w.y * d.y + w.z * d.z + w.w * d.w;
    }
    g_xb[g] = acc + b_ih[g] + b_hh[g];
}

// ---------------- phase 1: LSTM scan, 8-CTA cluster per batch --------------
// Lightweight flag protocol (NO mbarrier / cluster.sync / fences in loop):
//   producer thread: weak remote h store, then st.release of a step-stamped
//   flag (one writer per slot). Consumer warp w acquire-polls rank w's 32
//   flags (>= t, monotone), then __syncthreads chains visibility CTA-wide.
// Safety: a producer reaches step t+1 only after every CTA's flags for h(t),
// which are stored after that CTA's post-GEMV __syncthreads — so no buffer
// is overwritten while any CTA still reads it (same skew bound as R12/R13).
__global__ void __cluster_dims__(8, 1, 1) __launch_bounds__(256, 1)
k_lstm(const float* __restrict__ w_hh, const float* __restrict__ z_g,
       const float* __restrict__ h0) {
    int tid = threadIdx.x;
    uint32_t rk;
    asm("mov.u32 %0, %%cluster_ctarank;" : "=r"(rk));
    int b = blockIdx.x >> 3;

    __shared__ __align__(16) float h_sm[2][MM];       // cluster-written h
    __shared__ __align__(16) uint32_t flg[2][MM];     // per-value step flags
    __shared__ __align__(16) float gact[128];         // activated gates
    __shared__ __align__(16) float h_tmp[32];         // fresh h for broadcast

    // gate shard: row rloc = tid>>1, kh = K-half; math identical to R8..R13
    int rloc = tid >> 1;
    int kh = tid & 1;
    int g4 = rloc >> 5, j = rloc & 31;
    int grow = g4 * 256 + (int)rk * 32 + j;
    uint64_t wg[64];
    {
        const uint64_t* wp = (const uint64_t*)(w_hh + (size_t)grow * MM + kh * 128);
#pragma unroll
        for (int i = 0; i < 64; i++) wg[i] = wp[i];
    }
    float xb = g_xb[grow];

    // broadcast mapping: thread -> (target rank, value index)
    int rt = tid >> 5;          // target rank (8 ranks x 32 values)
    int idx = tid & 31;         // value index within owner warp
    uint32_t da, fa;            // remote data/flag base (buffer 0)
    {
        uint32_t slot = (uint32_t)(((int)rk * 32 + idx) * 4);
        da = mapa_rank(smem_u32(&h_sm[0][0]), (uint32_t)rt) + slot;
        fa = mapa_rank(smem_u32(&flg[0][0]), (uint32_t)rt) + slot;
    }
    // local poll address: warp w watches rank w's 32 flags
    int lane = tid & 31, warp = tid >> 5;
    uint32_t pa = smem_u32(&flg[0][0]) + (uint32_t)((warp * 32 + lane) * 4);

    h_sm[0][tid] = h0[tid];
    flg[0][tid] = 0; flg[1][tid] = 0;
    float c_reg = 0.f;
    if (tid < 32) c_reg = z_g[b * MM + (int)rk * 32 + tid];
    __syncthreads();
    cluster_sync_();   // flags zeroed everywhere before any remote flag store

    float* Hb = g_H + (size_t)b * NN * MM;

    for (int t = 0; t < NN; t++) {
        if (t > 0) {
            // h(t-1) certified: flag value t (monotone) in buffer t&1
            uint32_t a = pa + (uint32_t)((t & 1) * MM * 4);
            while ((int)ld_acquire_u32(a) < t) { }
        }
        __syncthreads();   // all ranks certified by some warp -> visible to CTA

        // ---- gate GEMV + fused activation (kh==0 thread applies act) ------
        {
            const ulonglong2* h4 = (const ulonglong2*)(h_sm[t & 1] + kh * 128);
            uint64_t a0 = 0, a1 = 0, a2 = 0, a3 = 0;
#pragma unroll
            for (int i = 0; i < 32; i += 2) {
                ulonglong2 v0 = h4[i], v1 = h4[i + 1];
                a0 = fma2(wg[2 * i + 0], v0.x, a0);
                a1 = fma2(wg[2 * i + 1], v0.y, a1);
                a2 = fma2(wg[2 * i + 2], v1.x, a2);
                a3 = fma2(wg[2 * i + 3], v1.y, a3);
            }
            float s = unpack_sum(add2(add2(a0, a1), add2(a2, a3)));
            s += __shfl_xor_sync(0xffffffffu, s, 1);
            if (kh == 0) {
                float v = s + xb;
                gact[rloc] = (g4 == 2) ? tanhf(v) : sigm(v);  // g4 warp-uniform
            }
        }
        __syncthreads();

        // ---- owner c/h update (warp 0) ------------------------------------
        if (tid < 32) {
            float ai = gact[tid], af = gact[32 + tid];
            float ag = gact[64 + tid], ao = gact[96 + tid];
            float c = af * c_reg + ai * ag;
            c_reg = c;
            float hv = ao * tanhf(c);
            Hb[(size_t)t * MM + (int)rk * 32 + tid] = hv;
            h_tmp[tid] = hv;
        }
        __syncthreads();

        // ---- broadcast: 256 threads, one remote value + release flag each --
        if (t + 1 < NN) {
            float hv = h_tmp[idx];
            uint32_t off = (uint32_t)(((t + 1) & 1) * MM * 4);
            st_cluster_f32(da + off, hv);            // weak data store
            st_release_u32(fa + off, (uint32_t)(t + 1));  // orders my data store
        }
    }
}

// ---------------- phase 2: C = A @ B^T (+bias), K=256, packed f32x2 --------
__global__ void __launch_bounds__(256) k_gemm_nt(
    const float* __restrict__ A, const float* __restrict__ B,
    const float* __restrict__ bias, float* __restrict__ C,
    size_t sA, size_t sB, size_t sC, int ldc) {
    A += (size_t)blockIdx.z * sA;
    B += (size_t)blockIdx.z * sB;
    C += (size_t)blockIdx.z * sC;
    int row0 = blockIdx.y * 128, col0 = blockIdx.x * 128;

    __shared__ __align__(16) float As[16][132];
    __shared__ __align__(16) float Bs[16][132];

    int tid = threadIdx.x;
    int tx = tid & 15, ty = tid >> 4;
    uint64_t acc2[8][4] = {};

    for (int kt = 0; kt < 256; kt += 16) {
#pragma unroll
        for (int l = 0; l < 2; l++) {
            int f = tid + 256 * l;
            int i = f >> 2, c4 = (f & 3) * 4;
            float4 a = *(const float4*)(A + (size_t)(row0 + i) * 256 + kt + c4);
            As[c4 + 0][i] = a.x; As[c4 + 1][i] = a.y; As[c4 + 2][i] = a.z; As[c4 + 3][i] = a.w;
            float4 bv = *(const float4*)(B + (size_t)(col0 + i) * 256 + kt + c4);
            Bs[c4 + 0][i] = bv.x; Bs[c4 + 1][i] = bv.y; Bs[c4 + 2][i] = bv.z; Bs[c4 + 3][i] = bv.w;
        }
        __syncthreads();
#pragma unroll
        for (int kk = 0; kk < 16; kk++) {
            float4 t0 = *(const float4*)(&As[kk][ty * 8]);
            float4 t1 = *(const float4*)(&As[kk][ty * 8 + 4]);
            uint64_t ad[8];
            ad[0] = pack2(t0.x, t0.x); ad[1] = pack2(t0.y, t0.y);
            ad[2] = pack2(t0.z, t0.z); ad[3] = pack2(t0.w, t0.w);
            ad[4] = pack2(t1.x, t1.x); ad[5] = pack2(t1.y, t1.y);
            ad[6] = pack2(t1.z, t1.z); ad[7] = pack2(t1.w, t1.w);
            const uint64_t* bsp = (const uint64_t*)(&Bs[kk][tx * 8]);
            uint64_t bp0 = bsp[0], bp1 = bsp[1], bp2 = bsp[2], bp3 = bsp[3];
#pragma unroll
            for (int i = 0; i < 8; i++) {
                acc2[i][0] = fma2(ad[i], bp0, acc2[i][0]);
                acc2[i][1] = fma2(ad[i], bp1, acc2[i][1]);
                acc2[i][2] = fma2(ad[i], bp2, acc2[i][2]);
                acc2[i][3] = fma2(ad[i], bp3, acc2[i][3]);
            }
        }
        __syncthreads();
    }

    float bs[8];
#pragma unroll
    for (int jj = 0; jj < 8; jj++) bs[jj] = bias ? bias[col0 + tx * 8 + jj] : 0.f;

#pragma unroll
    for (int i = 0; i < 8; i++) {
        float v[8];
#pragma unroll
        for (int jp = 0; jp < 4; jp++) unpack2(acc2[i][jp], v[2 * jp], v[2 * jp + 1]);
        float* cp = C + (size_t)(row0 + ty * 8 + i) * ldc + col0 + tx * 8;
        float4 v0 = make_float4(v[0] + bs[0], v[1] + bs[1], v[2] + bs[2], v[3] + bs[3]);
        float4 v1 = make_float4(v[4] + bs[4], v[5] + bs[5], v[6] + bs[6], v[7] + bs[7]);
        *(float4*)cp = v0;
        *(float4*)(cp + 4) = v1;
    }
}

// ---------------- phase 3a: serial masked-argmax chain (selection only) ----
__global__ void __launch_bounds__(1024, 1) k_select(const float* __restrict__ S) {
    int b = blockIdx.x;
    int tid = threadIdx.x;
    int lane = tid & 31, warp = tid >> 5;
    const float* base = S + (size_t)b * NN * NN;
    int n0 = tid * 2;
    bool u0 = false, u1 = false;
    int* rkb = g_rank + b * NN;

    __shared__ uint32_t kmax_s[2][32];
    __shared__ uint32_t kidx_s[2][32];

    auto step = [&](int t, float2 cur) {
        uint32_t k0 = u0 ? 0u : fkey(cur.x);
        uint32_t k1 = u1 ? 0u : fkey(cur.y);
        uint32_t km = k0 > k1 ? k0 : k1;
        uint32_t wmax = __reduce_max_sync(0xffffffffu, km);
        uint32_t ci = 0xffffffffu;
        if (k0 == wmax) ci = (uint32_t)n0;
        else if (k1 == wmax) ci = (uint32_t)(n0 + 1);
        uint32_t widx = __reduce_min_sync(0xffffffffu, ci);
        if (lane == 0) { kmax_s[t & 1][warp] = wmax; kidx_s[t & 1][warp] = widx; }
        __syncthreads();
        uint32_t vm = kmax_s[t & 1][lane];
        uint32_t vi = kidx_s[t & 1][lane];
        uint32_t gmax = __reduce_max_sync(0xffffffffu, vm);
        uint32_t ci2 = (vm == gmax) ? vi : 0xffffffffu;
        uint32_t gidx = __reduce_min_sync(0xffffffffu, ci2);
        if (gidx == (uint32_t)n0)            { u0 = true; rkb[n0] = t; }
        else if (gidx == (uint32_t)(n0 + 1)) { u1 = true; rkb[n0 + 1] = t; }
    };

    float2 r0 = *(const float2*)(base + (size_t)0 * NN + n0);
    float2 r1 = *(const float2*)(base + (size_t)1 * NN + n0);
    float2 r2 = *(const float2*)(base + (size_t)2 * NN + n0);
    float2 r3 = *(const float2*)(base + (size_t)3 * NN + n0);

    for (int t = 0; t < NN; t += 4) {
        step(t + 0, r0);
        if (t + 4 < NN) r0 = *(const float2*)(base + (size_t)(t + 4) * NN + n0);
        step(t + 1, r1);
        if (t + 5 < NN) r1 = *(const float2*)(base + (size_t)(t + 5) * NN + n0);
        step(t + 2, r2);
        if (t + 6 < NN) r2 = *(const float2*)(base + (size_t)(t + 6) * NN + n0);
        step(t + 3, r3);
        if (t + 7 < NN) r3 = *(const float2*)(base + (size_t)(t + 7) * NN + n0);
    }
}

// ---------------- phase 3b: fully parallel masked softmax ------------------
__global__ void __launch_bounds__(256) k_probs(float* __restrict__ out) {
    int t = blockIdx.x, b = blockIdx.y;
    float* row = out + ((size_t)b * NN + t) * NN;
    const int* rkb = g_rank + b * NN;
    int tid = threadIdx.x;
    int lane = tid & 31, warp = tid >> 5;

    __shared__ float ps[8];
    float e[8];
    float s = 0.f;
#pragma unroll
    for (int jj = 0; jj < 2; jj++) {
        int i = tid * 4 + jj * 1024;
        float4 v = *(const float4*)(row + i);
        int4 r = *(const int4*)(rkb + i);
        float e0 = (r.x >= t) ? __expf(v.x) : 0.f;
        float e1 = (r.y >= t) ? __expf(v.y) : 0.f;
        float e2 = (r.z >= t) ? __expf(v.z) : 0.f;
        float e3 = (r.w >= t) ? __expf(v.w) : 0.f;
        e[jj * 4 + 0] = e0; e[jj * 4 + 1] = e1;
        e[jj * 4 + 2] = e2; e[jj * 4 + 3] = e3;
        s += (e0 + e1) + (e2 + e3);
    }
#pragma unroll
    for (int m = 16; m; m >>= 1) s += __shfl_xor_sync(0xffffffffu, s, m);
    if (lane == 0) ps[warp] = s;
    __syncthreads();
    float tot = ((ps[0] + ps[1]) + (ps[2] + ps[3]))
              + ((ps[4] + ps[5]) + (ps[6] + ps[7]));
    float inv = __fdividef(1.f, tot);
#pragma unroll
    for (int jj = 0; jj < 2; jj++) {
        int i = tid * 4 + jj * 1024;
        *(float4*)(row + i) = make_float4(e[jj * 4 + 0] * inv, e[jj * 4 + 1] * inv,
                                          e[jj * 4 + 2] * inv, e[jj * 4 + 3] * inv);
    }
}

// ---------------- launch ---------------------------------------------------
extern "C" void kernel_launch(void* const* d_in, const int* in_sizes, int n_in,
                              void* d_out, int out_size) {
    const float* node = (const float*)d_in[0];
    const float* z_g  = (const float*)d_in[1];
    const float* dec  = (const float*)d_in[2];
    const float* h0   = (const float*)d_in[3];
    const float* w_ih = (const float*)d_in[4];
    const float* w_hh = (const float*)d_in[5];
    const float* b_ih = (const float*)d_in[6];
    const float* b_hh = (const float*)d_in[7];
    const float* Wq   = (const float*)d_in[8];
    const float* bq   = (const float*)d_in[9];
    const float* Wk   = (const float*)d_in[10];
    const float* bk   = (const float*)d_in[11];
    float* out = (float*)d_out;

    float* dH = nullptr;
    float* dQ = nullptr;
    float* dK = nullptr;
    cudaGetSymbolAddress((void**)&dH, g_H);
    cudaGetSymbolAddress((void**)&dQ, g_Q);
    cudaGetSymbolAddress((void**)&dK, g_K);

    // #1 keys = node_emb @ Wk^T + bk
    k_gemm_nt<<<dim3(2, 128, 1), 256>>>(node, Wk, bk, dK, 0, 0, 0, 256);

    // #2 setup (x_proj + biases)
    k_setup<<<1, 1024>>>(w_ih, b_ih, b_hh, dec);

    // #3 dummy (positions k_lstm as launch #4 for the ncu capture window)
    k_dummy<<<1, 32>>>();

    // #4 LSTM scan -> g_H
    k_lstm<<<64, 256>>>(w_hh, z_g, h0);

    // #5 Q = H @ Wq^T + bq
    k_gemm_nt<<<dim3(2, 128, 1), 256>>>(dH, Wq, bq, dQ, 0, 0, 0, 256);

    // #6 S = Q @ K^T straight into d_out (per batch)
    k_gemm_nt<<<dim3(16, 16, 8), 256>>>(dQ, dK, nullptr, out,
                                        (size_t)NN * MM, (size_t)NN * MM,
                                        (size_t)NN * NN, NN);

    // #7 serial selection chain -> g_rank
    k_select<<<8, 1024>>>(out);

    // #8 fully parallel masked softmax, in place
    k_probs<<<dim3(NN, NB), 256>>>(out);
}